// round 2
// baseline (speedup 1.0000x reference)
#include <cuda_runtime.h>

#define NUM_EXPERTS 64
#define TOPK 2
#define CAP 128
#define BATCH 8
#define SEQ 4096
#define HID 4096
#define M_TOKENS (BATCH * SEQ)                 /* 32768 */
#define BSE ((size_t)M_TOKENS * NUM_EXPERTS)   /* 2097152 */

typedef unsigned long long u64;

/* ------------ device scratch (static, allocation-free) ------------- */
__device__ float  g_logits[M_TOKENS * NUM_EXPERTS];  /* 8 MB */
__device__ int    g_sidx[M_TOKENS * TOPK];
__device__ float  g_sw[M_TOKENS * TOPK];
__device__ double g_acc[2];                          /* aux, z */

/* ------------ packed f32x2 helpers -------------------------------- */
__device__ __forceinline__ u64 fma2(u64 a, u64 b, u64 c) {
    u64 d;
    asm("fma.rn.f32x2 %0, %1, %2, %3;" : "=l"(d) : "l"(a), "l"(b), "l"(c));
    return d;
}
__device__ __forceinline__ float2 unpack2(u64 a) {
    float2 f;
    asm("mov.b64 {%0, %1}, %2;" : "=f"(f.x), "=f"(f.y) : "l"(a));
    return f;
}

/* =========================== K0: zero fill ========================== */
__global__ void zero_kernel(float4* dc) {
    size_t i = (size_t)blockIdx.x * blockDim.x + threadIdx.x;
    const size_t n4 = (2 * BSE) / 4;  /* dispatch + combine regions */
    float4 z = make_float4(0.f, 0.f, 0.f, 0.f);
    for (size_t j = i; j < n4; j += (size_t)gridDim.x * blockDim.x) dc[j] = z;
    if (i == 0) { g_acc[0] = 0.0; g_acc[1] = 0.0; }
}

/* =========================== K1: router GEMM ======================== */
/* logits[M,64] = hidden[M,4096] @ weight[64,4096]^T, fp32, f32x2 FMA.
 * Block: 256 thr, 64 tokens x 64 experts. Thread: 2 tokens x 8 experts,
 * accumulators packed over k-parity (even/odd partial sums). */
#define TM 64
#define KT 64
#define HS_STRIDE 66   /* 66 ≡ 2 (mod 32): LDS.64 h-loads hit 2-phase minimum */
#define WS_STRIDE 68   /* 16B-aligned float4 stores; loads are warp-broadcast */

__global__ void __launch_bounds__(256)
gemm_kernel(const float* __restrict__ hidden, const float* __restrict__ weight) {
    __shared__ float hs[TM * HS_STRIDE];
    __shared__ float ws[NUM_EXPERTS * WS_STRIDE];

    const int tid = threadIdx.x;
    const int tx = tid & 31, ty = tid >> 5;
    const int e0 = ty * 8;
    const int base = blockIdx.x * TM;

    u64 acc0[8], acc1[8];
#pragma unroll
    for (int j = 0; j < 8; j++) { acc0[j] = 0ull; acc1[j] = 0ull; }

    for (int k0 = 0; k0 < HID; k0 += KT) {
        __syncthreads();
        /* hidden tile: 64 tok x 64 k = 1024 float4, coalesced */
#pragma unroll
        for (int p = 0; p < 4; p++) {
            int li = tid + p * 256;
            int tt = li >> 4, kq = li & 15;
            float4 v = *(const float4*)&hidden[(size_t)(base + tt) * HID + k0 + kq * 4];
            *(float2*)&hs[tt * HS_STRIDE + kq * 4]     = make_float2(v.x, v.y);
            *(float2*)&hs[tt * HS_STRIDE + kq * 4 + 2] = make_float2(v.z, v.w);
        }
        /* weight tile: 64 e x 64 k (L2-resident), coalesced */
#pragma unroll
        for (int p = 0; p < 4; p++) {
            int li = tid + p * 256;
            int ee = li >> 4, kq = li & 15;
            *(float4*)&ws[ee * WS_STRIDE + kq * 4] =
                *(const float4*)&weight[(size_t)ee * HID + k0 + kq * 4];
        }
        __syncthreads();

#pragma unroll 4
        for (int kk = 0; kk < KT / 2; kk++) {
            u64 h0 = *(const u64*)&hs[tx * HS_STRIDE + 2 * kk];
            u64 h1 = *(const u64*)&hs[(tx + 32) * HS_STRIDE + 2 * kk];
            u64 w[8];
#pragma unroll
            for (int j = 0; j < 8; j++)
                w[j] = *(const u64*)&ws[(e0 + j) * WS_STRIDE + 2 * kk];
#pragma unroll
            for (int j = 0; j < 8; j++) {
                acc0[j] = fma2(h0, w[j], acc0[j]);
                acc1[j] = fma2(h1, w[j], acc1[j]);
            }
        }
    }

    float r0[8], r1[8];
#pragma unroll
    for (int j = 0; j < 8; j++) {
        float2 a = unpack2(acc0[j]); r0[j] = a.x + a.y;
        float2 b = unpack2(acc1[j]); r1[j] = b.x + b.y;
    }
    size_t o0 = (size_t)(base + tx) * 64 + e0;
    size_t o1 = (size_t)(base + tx + 32) * 64 + e0;
    *(float4*)&g_logits[o0]     = make_float4(r0[0], r0[1], r0[2], r0[3]);
    *(float4*)&g_logits[o0 + 4] = make_float4(r0[4], r0[5], r0[6], r0[7]);
    *(float4*)&g_logits[o1]     = make_float4(r1[0], r1[1], r1[2], r1[3]);
    *(float4*)&g_logits[o1 + 4] = make_float4(r1[4], r1[5], r1[6], r1[7]);
}

/* ================= K2: softmax + top-2 + probs + losses ============= */
/* 1 warp = 1 token (2 experts per lane). 8 tokens / 256-thread block.  */
__global__ void softmax_topk_kernel(float* __restrict__ probs_out) {
    const unsigned FULL = 0xffffffffu;
    int tid = threadIdx.x;
    int lane = tid & 31, wid = tid >> 5;
    int token = blockIdx.x * 8 + wid;
    const float* lp = &g_logits[(size_t)token * 64];
    float l0 = lp[lane], l1 = lp[lane + 32];

    float m = fmaxf(l0, l1);
#pragma unroll
    for (int off = 16; off; off >>= 1)
        m = fmaxf(m, __shfl_xor_sync(FULL, m, off));

    float p0 = __expf(l0 - m), p1 = __expf(l1 - m);
    float s = p0 + p1;
#pragma unroll
    for (int off = 16; off; off >>= 1) s += __shfl_xor_sync(FULL, s, off);
    float inv = 1.f / s;

    probs_out[(size_t)token * 64 + lane]      = p0 * inv;
    probs_out[(size_t)token * 64 + lane + 32] = p1 * inv;

    float sq = p0 * p0 + p1 * p1;
#pragma unroll
    for (int off = 16; off; off >>= 1) sq += __shfl_xor_sync(FULL, sq, off);
    sq = sq * inv * inv;                 /* sum of normalized probs^2 */
    float lse = m + __logf(s);

    /* top-1 (lower index wins ties) */
    float v1 = p0; int i1 = lane;
    if (p1 > v1) { v1 = p1; i1 = lane + 32; }
#pragma unroll
    for (int off = 16; off; off >>= 1) {
        float ov = __shfl_xor_sync(FULL, v1, off);
        int   oi = __shfl_xor_sync(FULL, i1, off);
        if (ov > v1 || (ov == v1 && oi < i1)) { v1 = ov; i1 = oi; }
    }
    /* top-2: exclude i1 (probs > 0, so -1 acts as -inf) */
    float c0 = (lane == i1)      ? -1.f : p0;
    float c1 = (lane + 32 == i1) ? -1.f : p1;
    float v2 = c0; int i2 = lane;
    if (c1 > v2) { v2 = c1; i2 = lane + 32; }
#pragma unroll
    for (int off = 16; off; off >>= 1) {
        float ov = __shfl_xor_sync(FULL, v2, off);
        int   oi = __shfl_xor_sync(FULL, i2, off);
        if (ov > v2 || (ov == v2 && oi < i2)) { v2 = ov; i2 = oi; }
    }

    if (lane == 0) {
        float wsum = v1 + v2;            /* renormalized ratio == prob ratio */
        g_sidx[token * 2]     = i1;
        g_sidx[token * 2 + 1] = i2;
        g_sw[token * 2]       = v1 / wsum;
        g_sw[token * 2 + 1]   = v2 / wsum;
    }

    __shared__ double s_aux[8], s_z[8];
    if (lane == 0) { s_aux[wid] = (double)sq; s_z[wid] = (double)lse * (double)lse; }
    __syncthreads();
    if (tid == 0) {
        double a = 0.0, z = 0.0;
#pragma unroll
        for (int i = 0; i < 8; i++) { a += s_aux[i]; z += s_z[i]; }
        atomicAdd(&g_acc[0], a);
        atomicAdd(&g_acc[1], z);
    }
}

/* ============ K3: capacity-limited dispatch (k-major scan) ========== */
/* 1 block per batch; thread e owns expert e's counter; indices smem-resident. */
__global__ void dispatch_kernel(float* __restrict__ dispatch,
                                float* __restrict__ combine,
                                float* __restrict__ losses) {
    __shared__ int s_idx[SEQ * TOPK];   /* 32 KB */
    int b = blockIdx.x;
    int tid = threadIdx.x;
    for (int i = tid; i < SEQ * TOPK; i += blockDim.x)
        s_idx[i] = g_sidx[b * SEQ * TOPK + i];
    __syncthreads();

    if (tid < NUM_EXPERTS) {
        int e = tid, cnt = 0;
        for (int k = 0; k < TOPK; k++) {
            for (int s = 0; s < SEQ; s += 16) {
                int v[16];
#pragma unroll
                for (int u = 0; u < 16; u++) v[u] = s_idx[(s + u) * 2 + k];
#pragma unroll
                for (int u = 0; u < 16; u++) {
                    if (v[u] == e) {
                        if (cnt < CAP) {
                            int t = b * SEQ + s + u;
                            size_t o = (size_t)t * 64 + e;
                            dispatch[o] = 1.0f;
                            combine[o]  = g_sw[t * 2 + k];
                        }
                        cnt++;
                    }
                }
            }
        }
    }
    if (b == 0 && tid == NUM_EXPERTS) {   /* runs after K2 in-stream */
        losses[0] = (float)(g_acc[0] * ((double)NUM_EXPERTS / (double)M_TOKENS));
        losses[1] = (float)(g_acc[1] / (double)M_TOKENS);
    }
}

/* ============================ launch ================================ */
extern "C" void kernel_launch(void* const* d_in, const int* in_sizes, int n_in,
                              void* d_out, int out_size) {
    const float* hidden = (const float*)d_in[0];
    const float* weight = (const float*)d_in[1];
    if (n_in >= 2 && in_sizes[0] < in_sizes[1]) {  /* defensive order check */
        hidden = (const float*)d_in[1];
        weight = (const float*)d_in[0];
    }
    float* out      = (float*)d_out;
    float* dispatch = out;
    float* combine  = out + BSE;
    float* probs    = out + 2 * BSE;
    float* losses   = out + 3 * BSE;

    zero_kernel<<<2048, 256>>>((float4*)out);
    gemm_kernel<<<M_TOKENS / TM, 256>>>(hidden, weight);
    softmax_topk_kernel<<<M_TOKENS / 8, 256>>>(probs);
    dispatch_kernel<<<BATCH, 128>>>(dispatch, combine, losses);
}

// round 3
// speedup vs baseline: 2.1946x; 2.1946x over previous
#include <cuda_runtime.h>

#define NUM_EXPERTS 64
#define TOPK 2
#define CAP 128
#define BATCH 8
#define SEQ 4096
#define HID 4096
#define M_TOKENS (BATCH * SEQ)                 /* 32768 */
#define BSE ((size_t)M_TOKENS * NUM_EXPERTS)   /* 2097152 */

typedef unsigned long long u64;

/* ------------ device scratch (static, allocation-free) ------------- */
__device__ float  g_logits[M_TOKENS * NUM_EXPERTS];  /* 8 MB */
__device__ int    g_sidx[M_TOKENS * TOPK];
__device__ float  g_sw[M_TOKENS * TOPK];
__device__ double g_acc[2];                          /* aux, z */

/* ------------ packed f32x2 helpers -------------------------------- */
__device__ __forceinline__ u64 fma2(u64 a, u64 b, u64 c) {
    u64 d;
    asm("fma.rn.f32x2 %0, %1, %2, %3;" : "=l"(d) : "l"(a), "l"(b), "l"(c));
    return d;
}
__device__ __forceinline__ float2 unpack2(u64 a) {
    float2 f;
    asm("mov.b64 {%0, %1}, %2;" : "=f"(f.x), "=f"(f.y) : "l"(a));
    return f;
}

/* =========================== K0: zero fill ========================== */
__global__ void zero_kernel(float4* dc) {
    size_t i = (size_t)blockIdx.x * blockDim.x + threadIdx.x;
    const size_t n4 = (2 * BSE) / 4;  /* dispatch + combine regions */
    float4 z = make_float4(0.f, 0.f, 0.f, 0.f);
    for (size_t j = i; j < n4; j += (size_t)gridDim.x * blockDim.x) dc[j] = z;
    if (i == 0) { g_acc[0] = 0.0; g_acc[1] = 0.0; }
}

/* =========================== K1: router GEMM ======================== */
/* logits[M,64] = hidden[M,4096] @ weight[64,4096]^T, fp32, FFMA2.
 * Block 256 thr: 128 tokens x 64 experts. Thread: 4 tokens x 8 experts,
 * accumulators packed over k-parity. LDS.128 feeds, stride 36 (=4 mod 32)
 * hits the 4-phase minimum; weight loads are warp-broadcast (1 phase). */
#define TM 128
#define KT 32
#define HS2 36

__global__ void __launch_bounds__(256, 2)
gemm_kernel(const float* __restrict__ hidden, const float* __restrict__ weight) {
    __shared__ float hs[TM * HS2];          /* 18,432 B */
    __shared__ float ws[NUM_EXPERTS * KT];  /*  8,192 B */

    const int tid = threadIdx.x;
    const int tx = tid & 31, ty = tid >> 5;
    const int e0 = ty * 8;
    const int base = blockIdx.x * TM;

    u64 acc[4][8];
#pragma unroll
    for (int m = 0; m < 4; m++)
#pragma unroll
        for (int j = 0; j < 8; j++) acc[m][j] = 0ull;

    const int tt0 = tid >> 3, kq0 = tid & 7;

    for (int k0 = 0; k0 < HID; k0 += KT) {
        __syncthreads();
        /* hidden tile: 128 tok x 32 k, coalesced float4 */
#pragma unroll
        for (int p = 0; p < 4; p++) {
            int tt = tt0 + p * 32;
            *(float4*)&hs[tt * HS2 + kq0 * 4] =
                *(const float4*)&hidden[(size_t)(base + tt) * HID + k0 + kq0 * 4];
        }
        /* weight tile: 64 e x 32 k (L2-resident) */
#pragma unroll
        for (int p = 0; p < 2; p++) {
            int ee = tt0 + p * 32;
            *(float4*)&ws[ee * KT + kq0 * 4] =
                *(const float4*)&weight[(size_t)ee * HID + k0 + kq0 * 4];
        }
        __syncthreads();

#pragma unroll
        for (int q = 0; q < KT / 4; q++) {
            longlong2 h[4];
#pragma unroll
            for (int m = 0; m < 4; m++)
                h[m] = *(const longlong2*)&hs[(tx + 32 * m) * HS2 + 4 * q];
#pragma unroll
            for (int j = 0; j < 8; j++) {
                longlong2 w = *(const longlong2*)&ws[(e0 + j) * KT + 4 * q];
#pragma unroll
                for (int m = 0; m < 4; m++) {
                    acc[m][j] = fma2((u64)h[m].x, (u64)w.x, acc[m][j]);
                    acc[m][j] = fma2((u64)h[m].y, (u64)w.y, acc[m][j]);
                }
            }
        }
    }

#pragma unroll
    for (int m = 0; m < 4; m++) {
        float r[8];
#pragma unroll
        for (int j = 0; j < 8; j++) {
            float2 a = unpack2(acc[m][j]);
            r[j] = a.x + a.y;
        }
        size_t o = (size_t)(base + tx + 32 * m) * 64 + e0;
        *(float4*)&g_logits[o]     = make_float4(r[0], r[1], r[2], r[3]);
        *(float4*)&g_logits[o + 4] = make_float4(r[4], r[5], r[6], r[7]);
    }
}

/* ================= K2: softmax + top-2 + probs + losses ============= */
/* 1 warp = 1 token (2 experts per lane). 8 tokens / 256-thread block.  */
__global__ void softmax_topk_kernel(float* __restrict__ probs_out) {
    const unsigned FULL = 0xffffffffu;
    int tid = threadIdx.x;
    int lane = tid & 31, wid = tid >> 5;
    int token = blockIdx.x * 8 + wid;
    const float* lp = &g_logits[(size_t)token * 64];
    float l0 = lp[lane], l1 = lp[lane + 32];

    float m = fmaxf(l0, l1);
#pragma unroll
    for (int off = 16; off; off >>= 1)
        m = fmaxf(m, __shfl_xor_sync(FULL, m, off));

    float p0 = __expf(l0 - m), p1 = __expf(l1 - m);
    float s = p0 + p1;
#pragma unroll
    for (int off = 16; off; off >>= 1) s += __shfl_xor_sync(FULL, s, off);
    float inv = 1.f / s;

    probs_out[(size_t)token * 64 + lane]      = p0 * inv;
    probs_out[(size_t)token * 64 + lane + 32] = p1 * inv;

    float sq = p0 * p0 + p1 * p1;
#pragma unroll
    for (int off = 16; off; off >>= 1) sq += __shfl_xor_sync(FULL, sq, off);
    sq = sq * inv * inv;
    float lse = m + __logf(s);

    /* top-1 (lower index wins ties) */
    float v1 = p0; int i1 = lane;
    if (p1 > v1) { v1 = p1; i1 = lane + 32; }
#pragma unroll
    for (int off = 16; off; off >>= 1) {
        float ov = __shfl_xor_sync(FULL, v1, off);
        int   oi = __shfl_xor_sync(FULL, i1, off);
        if (ov > v1 || (ov == v1 && oi < i1)) { v1 = ov; i1 = oi; }
    }
    /* top-2: exclude i1 (probs > 0, so -1 acts as -inf) */
    float c0 = (lane == i1)      ? -1.f : p0;
    float c1 = (lane + 32 == i1) ? -1.f : p1;
    float v2 = c0; int i2 = lane;
    if (c1 > v2) { v2 = c1; i2 = lane + 32; }
#pragma unroll
    for (int off = 16; off; off >>= 1) {
        float ov = __shfl_xor_sync(FULL, v2, off);
        int   oi = __shfl_xor_sync(FULL, i2, off);
        if (ov > v2 || (ov == v2 && oi < i2)) { v2 = ov; i2 = oi; }
    }

    if (lane == 0) {
        float wsum = v1 + v2;
        g_sidx[token * 2]     = i1;
        g_sidx[token * 2 + 1] = i2;
        g_sw[token * 2]       = v1 / wsum;
        g_sw[token * 2 + 1]   = v2 / wsum;
    }

    __shared__ double s_aux[8], s_z[8];
    if (lane == 0) { s_aux[wid] = (double)sq; s_z[wid] = (double)lse * (double)lse; }
    __syncthreads();
    if (tid == 0) {
        double a = 0.0, z = 0.0;
#pragma unroll
        for (int i = 0; i < 8; i++) { a += s_aux[i]; z += s_z[i]; }
        atomicAdd(&g_acc[0], a);
        atomicAdd(&g_acc[1], z);
    }
}

/* ====== K3: capacity dispatch — 1 warp per (batch, expert), ballot == */
__global__ void __launch_bounds__(256)
dispatch_kernel(float* __restrict__ dispatch,
                float* __restrict__ combine,
                float* __restrict__ losses) {
    const unsigned FULL = 0xffffffffu;
    int gw = (blockIdx.x * blockDim.x + threadIdx.x) >> 5;  /* 0..511 */
    int lane = threadIdx.x & 31;
    int b = gw >> 6, e = gw & 63;

    const int*   idx = &g_sidx[b * SEQ * TOPK];
    const float* swp = &g_sw[b * SEQ * TOPK];
    unsigned lt = (1u << lane) - 1u;
    int cnt = 0;

#pragma unroll
    for (int k = 0; k < TOPK; k++) {
        for (int s0 = 0; s0 < SEQ; s0 += 128) {
            int v[4];
#pragma unroll
            for (int u = 0; u < 4; u++)
                v[u] = idx[(s0 + u * 32 + lane) * 2 + k];
#pragma unroll
            for (int u = 0; u < 4; u++) {
                unsigned msk = __ballot_sync(FULL, v[u] == e);
                if (v[u] == e) {
                    int r = cnt + __popc(msk & lt);
                    if (r < CAP) {
                        int sl = s0 + u * 32 + lane;
                        int t = b * SEQ + sl;
                        size_t o = (size_t)t * 64 + e;
                        dispatch[o] = 1.0f;
                        combine[o]  = swp[sl * 2 + k];
                    }
                }
                cnt += __popc(msk);
            }
        }
    }

    if (gw == 0 && lane == 0) {  /* g_acc finalized by K2 (prior launch) */
        losses[0] = (float)(g_acc[0] * ((double)NUM_EXPERTS / (double)M_TOKENS));
        losses[1] = (float)(g_acc[1] / (double)M_TOKENS);
    }
}

/* ============================ launch ================================ */
extern "C" void kernel_launch(void* const* d_in, const int* in_sizes, int n_in,
                              void* d_out, int out_size) {
    const float* hidden = (const float*)d_in[0];
    const float* weight = (const float*)d_in[1];
    if (n_in >= 2 && in_sizes[0] < in_sizes[1]) {  /* defensive order check */
        hidden = (const float*)d_in[1];
        weight = (const float*)d_in[0];
    }
    float* out      = (float*)d_out;
    float* dispatch = out;
    float* combine  = out + BSE;
    float* probs    = out + 2 * BSE;
    float* losses   = out + 3 * BSE;

    zero_kernel<<<2048, 256>>>((float4*)out);
    gemm_kernel<<<M_TOKENS / TM, 256>>>(hidden, weight);
    softmax_topk_kernel<<<M_TOKENS / 8, 256>>>(probs);
    dispatch_kernel<<<64, 256>>>(dispatch, combine, losses);
}

// round 6
// speedup vs baseline: 5.7582x; 2.6238x over previous
#include <cuda_runtime.h>
#include <cuda_bf16.h>
#include <cstdint>

#define NUM_EXPERTS 64
#define TOPK 2
#define CAP 128
#define BATCH 8
#define SEQ 4096
#define HID 4096
#define M_TOKENS (BATCH * SEQ)                 /* 32768 */
#define BSE ((size_t)M_TOKENS * NUM_EXPERTS)   /* 2097152 */

/* ------------ device scratch (static, allocation-free) ------------- */
__device__ int             g_sidx[M_TOKENS * TOPK];
__device__ float           g_sw[M_TOKENS * TOPK];
__device__ double          g_acc[2];                 /* aux, z */
__device__ __nv_bfloat16   g_whi[NUM_EXPERTS * HID];
__device__ __nv_bfloat16   g_wlo[NUM_EXPERTS * HID];

/* ---------------------- helpers ------------------------------------ */
__device__ __forceinline__ uint32_t smem_u32(const void* p) {
    uint32_t a;
    asm("{ .reg .u64 t; cvta.to.shared.u64 t, %1; cvt.u32.u64 %0, t; }"
        : "=r"(a) : "l"(p));
    return a;
}
__device__ __forceinline__ void ldsm4(uint32_t* r, uint32_t addr) {
    asm volatile("ldmatrix.sync.aligned.m8n8.x4.shared.b16 {%0,%1,%2,%3}, [%4];"
        : "=r"(r[0]), "=r"(r[1]), "=r"(r[2]), "=r"(r[3]) : "r"(addr));
}
__device__ __forceinline__ void mma_bf16(float* d, const uint32_t* a,
                                         uint32_t b0, uint32_t b1) {
    asm volatile(
        "mma.sync.aligned.m16n8k16.row.col.f32.bf16.bf16.f32 "
        "{%0,%1,%2,%3}, {%4,%5,%6,%7}, {%8,%9}, {%0,%1,%2,%3};"
        : "+f"(d[0]), "+f"(d[1]), "+f"(d[2]), "+f"(d[3])
        : "r"(a[0]), "r"(a[1]), "r"(a[2]), "r"(a[3]), "r"(b0), "r"(b1));
}
__device__ __forceinline__ void cp16(uint32_t dst, const void* src) {
    asm volatile("cp.async.cg.shared.global [%0], [%1], 16;"
                 :: "r"(dst), "l"(src) : "memory");
}
__device__ __forceinline__ void cvt_hl(float a, float b, uint32_t& h, uint32_t& l) {
    __nv_bfloat162 hh = __float22bfloat162_rn(make_float2(a, b));
    float2 hf = __bfloat1622float2(hh);
    __nv_bfloat162 ll = __float22bfloat162_rn(make_float2(a - hf.x, b - hf.y));
    h = *(uint32_t*)&hh;
    l = *(uint32_t*)&ll;
}

/* =========================== K0: zero fill ========================== */
__global__ void zero_kernel(float4* dc) {
    size_t i = (size_t)blockIdx.x * blockDim.x + threadIdx.x;
    const size_t n4 = (2 * BSE) / 4;
    float4 z = make_float4(0.f, 0.f, 0.f, 0.f);
    for (size_t j = i; j < n4; j += (size_t)gridDim.x * blockDim.x) dc[j] = z;
    if (i == 0) { g_acc[0] = 0.0; g_acc[1] = 0.0; }
}

/* ===================== K0b: split weights to bf16 =================== */
__global__ void prep_w_kernel(const float* __restrict__ w) {
    int i = blockIdx.x * 256 + threadIdx.x;   /* grid 1024 -> 262144 */
    float x = w[i];
    __nv_bfloat16 h = __float2bfloat16(x);
    g_whi[i] = h;
    g_wlo[i] = __float2bfloat16(x - __bfloat162float(h));
}

/* ===== K1: HMMA bf16-split GEMM + fused softmax/top2/losses ========= */
/* CTA: 128 tokens x 64 experts, 8 warps (16 rows each), K-chunk 64.   */
#define TM 128
#define KCH 64
#define NCHUNK (HID / KCH)
#define RS 144                     /* bytes per 64-bf16 row, padded    */
#define OFF_AL 18432               /* 128*144                          */
#define OFF_W  36864
#define W_LO   9216                /* 64*144                           */
#define W_BUF  18432
#define SMEM_GEMM (OFF_W + 2 * W_BUF)   /* 73728 */

__device__ __forceinline__ void cp_w(uint32_t wb, int k0, int wrow, int wkq) {
    const __nv_bfloat16* gh = g_whi + (size_t)wrow * HID + k0 + 16 * wkq;
    const __nv_bfloat16* gl = g_wlo + (size_t)wrow * HID + k0 + 16 * wkq;
    uint32_t off = wrow * RS + 32 * wkq;
    cp16(wb + off,             gh);
    cp16(wb + off + 16,        gh + 8);
    cp16(wb + W_LO + off,      gl);
    cp16(wb + W_LO + off + 16, gl + 8);
}

__global__ void __launch_bounds__(256, 2)
gemm_kernel(const float* __restrict__ hidden, float* __restrict__ probs) {
    extern __shared__ char smem[];
    const uint32_t sb = smem_u32(smem);
    const int tid = threadIdx.x;
    const int lane = tid & 31, wid = tid >> 5;
    const int base = blockIdx.x * TM;
    const int R = wid * 16;

    float acc[32];
#pragma unroll
    for (int i = 0; i < 32; i++) acc[i] = 0.f;

    const int hrow = tid >> 4, hkq = tid & 15;       /* hidden ldg map  */
    const int wrow = tid >> 2, wkq = tid & 3;        /* weight cp map   */

    float4 h[8];
    {
        const float* hp = hidden + (size_t)(base + hrow) * HID + 4 * hkq;
#pragma unroll
        for (int p = 0; p < 8; p++)
            h[p] = __ldg((const float4*)(hp + (size_t)16 * p * HID));
        cp_w(sb + OFF_W, 0, wrow, wkq);
        asm volatile("cp.async.commit_group;" ::: "memory");
    }

    /* ldmatrix source addresses (per-lane, chunk-invariant parts) */
    const uint32_t aH = sb + (R + (lane & 15)) * RS + 16 * (lane >> 4);
    const uint32_t aL = aH + OFF_AL;
    const uint32_t bC = sb + OFF_W + (8 * (lane >> 4) + (lane & 7)) * RS
                        + 16 * ((lane >> 3) & 1);

    for (int c = 0; c < NCHUNK; c++) {
        const int s = c & 1;
        __syncthreads();                      /* prior MMA done with stage */
#pragma unroll
        for (int p = 0; p < 8; p++) {
            int row = hrow + 16 * p;
            uint32_t hi0, lo0, hi1, lo1;
            cvt_hl(h[p].x, h[p].y, hi0, lo0);
            cvt_hl(h[p].z, h[p].w, hi1, lo1);
            uint32_t off = row * RS + 8 * hkq;
            *(uint2*)(smem + off)          = make_uint2(hi0, hi1);
            *(uint2*)(smem + OFF_AL + off) = make_uint2(lo0, lo1);
        }
        asm volatile("cp.async.wait_group 0;" ::: "memory");
        __syncthreads();                      /* stage + weights visible   */

        if (c + 1 < NCHUNK) {                 /* prefetch, overlaps MMA    */
            const float* hp = hidden + (size_t)(base + hrow) * HID
                              + (c + 1) * KCH + 4 * hkq;
#pragma unroll
            for (int p = 0; p < 8; p++)
                h[p] = __ldg((const float4*)(hp + (size_t)16 * p * HID));
            cp_w(sb + OFF_W + ((c + 1) & 1) * W_BUF, (c + 1) * KCH, wrow, wkq);
            asm volatile("cp.async.commit_group;" ::: "memory");
        }

        const uint32_t bS = bC + s * W_BUF;
#pragma unroll
        for (int q = 0; q < 4; q++) {
            uint32_t ah[4], al[4];
            ldsm4(ah, aH + 32 * q);
            ldsm4(al, aL + 32 * q);
#pragma unroll
            for (int jp = 0; jp < 4; jp++) {
                uint32_t bh[4], bl[4];
                ldsm4(bh, bS + jp * (16 * RS) + 32 * q);
                ldsm4(bl, bS + W_LO + jp * (16 * RS) + 32 * q);
                mma_bf16(acc + 8 * jp,     ah, bh[0], bh[1]);
                mma_bf16(acc + 8 * jp,     ah, bl[0], bl[1]);
                mma_bf16(acc + 8 * jp,     al, bh[0], bh[1]);
                mma_bf16(acc + 8 * jp + 4, ah, bh[2], bh[3]);
                mma_bf16(acc + 8 * jp + 4, ah, bl[2], bl[3]);
                mma_bf16(acc + 8 * jp + 4, al, bh[2], bh[3]);
            }
        }
    }

    /* ---------------- epilogue: logits -> smem ---------------------- */
    __syncthreads();                          /* all warps done with A     */
    float* lg = (float*)smem;                 /* 128 rows x 72-float rows  */
    {
        int er = R + (lane >> 2), ec = 2 * (lane & 3);
#pragma unroll
        for (int j = 0; j < 8; j++) {
            *(float2*)&lg[er * 72 + 8 * j + ec]       = make_float2(acc[4*j],   acc[4*j+1]);
            *(float2*)&lg[(er + 8) * 72 + 8 * j + ec] = make_float2(acc[4*j+2], acc[4*j+3]);
        }
    }
    __syncthreads();

    double da = 0.0, dz = 0.0;
    if (tid < TM) {
        float l[64];
#pragma unroll
        for (int g = 0; g < 16; g++)
            *(float4*)&l[4 * g] = *(float4*)&lg[tid * 72 + 4 * g];

        float m = l[0];
#pragma unroll
        for (int j = 1; j < 64; j++) m = fmaxf(m, l[j]);
        float ssum = 0.f;
#pragma unroll
        for (int j = 0; j < 64; j++) { l[j] = __expf(l[j] - m); ssum += l[j]; }
        float inv = 1.f / ssum;
        float lse = m + __logf(ssum);

        float v1 = -1.f, v2 = -1.f, sq = 0.f;
        int i1 = 0, i2 = 0;
#pragma unroll
        for (int j = 0; j < 64; j++) {
            float p = l[j];
            sq += p * p;
            if (p > v1)      { v2 = v1; i2 = i1; v1 = p; i1 = j; }
            else if (p > v2) { v2 = p; i2 = j; }
        }
        sq *= inv * inv;

        const int token = base + tid;
#pragma unroll
        for (int g = 0; g < 16; g++) {
            float4 v = make_float4(l[4*g] * inv, l[4*g+1] * inv,
                                   l[4*g+2] * inv, l[4*g+3] * inv);
            *(float4*)&probs[(size_t)token * 64 + 4 * g] = v;
        }
        float wsum = v1 + v2;
        *(int2*)&g_sidx[token * 2]   = make_int2(i1, i2);
        *(float2*)&g_sw[token * 2]   = make_float2(v1 / wsum, v2 / wsum);

        da = (double)sq;
        dz = (double)lse * (double)lse;
    }

#pragma unroll
    for (int off = 16; off; off >>= 1) {
        da += __shfl_xor_sync(0xffffffffu, da, off);
        dz += __shfl_xor_sync(0xffffffffu, dz, off);
    }
    __syncthreads();
    double* red = (double*)(smem + OFF_W);    /* W region idle now */
    if (lane == 0) { red[wid] = da; red[8 + wid] = dz; }
    __syncthreads();
    if (tid == 0) {
        double a = 0.0, z = 0.0;
#pragma unroll
        for (int i = 0; i < 8; i++) { a += red[i]; z += red[8 + i]; }
        atomicAdd(&g_acc[0], a);
        atomicAdd(&g_acc[1], z);
    }
}

/* ====== K3: capacity dispatch — smem-staged ballot rank scan ======== */
__global__ void __launch_bounds__(256)
dispatch_kernel(float* __restrict__ dispatch,
                float* __restrict__ combine,
                float* __restrict__ losses) {
    extern __shared__ int ds[];            /* [8192] idx + [8192] sw = 64 KB */
    const unsigned FULL = 0xffffffffu;
    const int tid = threadIdx.x;
    const int lane = tid & 31, wid = tid >> 5;
    const int b = blockIdx.x >> 3;
    const int e = ((blockIdx.x & 7) << 3) + wid;

    {
        const int4* si = (const int4*)&g_sidx[b * SEQ * TOPK];
        const int4* sw = (const int4*)&g_sw[b * SEQ * TOPK];
        int4* di = (int4*)ds;
        int4* dw = (int4*)(ds + SEQ * TOPK);
#pragma unroll
        for (int p = 0; p < 8; p++) { di[tid + 256 * p] = si[tid + 256 * p];
                                      dw[tid + 256 * p] = sw[tid + 256 * p]; }
    }
    __syncthreads();
    const float* swp = (const float*)(ds + SEQ * TOPK);
    unsigned lt = (1u << lane) - 1u;
    int cnt = 0;

#pragma unroll
    for (int k = 0; k < TOPK; k++) {
        for (int s0 = 0; s0 < SEQ; s0 += 256) {
            int v[8];
#pragma unroll
            for (int u = 0; u < 8; u++) v[u] = ds[(s0 + u * 32 + lane) * 2 + k];
#pragma unroll
            for (int u = 0; u < 8; u++) {
                unsigned msk = __ballot_sync(FULL, v[u] == e);
                if (v[u] == e) {
                    int r = cnt + __popc(msk & lt);
                    if (r < CAP) {
                        int sl = s0 + u * 32 + lane;
                        size_t o = (size_t)(b * SEQ + sl) * 64 + e;
                        dispatch[o] = 1.0f;
                        combine[o]  = swp[sl * 2 + k];
                    }
                }
                cnt += __popc(msk);
            }
        }
    }

    if (blockIdx.x == 0 && tid == 0) {     /* g_acc finalized by K1 */
        losses[0] = (float)(g_acc[0] * ((double)NUM_EXPERTS / (double)M_TOKENS));
        losses[1] = (float)(g_acc[1] / (double)M_TOKENS);
    }
}

/* ============================ launch ================================ */
extern "C" void kernel_launch(void* const* d_in, const int* in_sizes, int n_in,
                              void* d_out, int out_size) {
    const float* hidden = (const float*)d_in[0];
    const float* weight = (const float*)d_in[1];
    if (n_in >= 2 && in_sizes[0] < in_sizes[1]) {
        hidden = (const float*)d_in[1];
        weight = (const float*)d_in[0];
    }
    float* out      = (float*)d_out;
    float* dispatch = out;
    float* combine  = out + BSE;
    float* probs    = out + 2 * BSE;
    float* losses   = out + 3 * BSE;

    cudaFuncSetAttribute(gemm_kernel,
                         cudaFuncAttributeMaxDynamicSharedMemorySize, SMEM_GEMM);
    cudaFuncSetAttribute(dispatch_kernel,
                         cudaFuncAttributeMaxDynamicSharedMemorySize, 65536);

    zero_kernel<<<2048, 256>>>((float4*)out);
    prep_w_kernel<<<1024, 256>>>(weight);
    gemm_kernel<<<M_TOKENS / TM, 256, SMEM_GEMM>>>(hidden, probs);
    dispatch_kernel<<<64, 256, 65536>>>(dispatch, combine, losses);
}